// round 9
// baseline (speedup 1.0000x reference)
#include <cuda_runtime.h>
#include <cuda_bf16.h>
#include <cstdint>

#define VOCAB 4
#define DIM   128
#define MAX_SEGS 8192
#define CHUNK 8                // tokens per thread; warp covers 256 tokens
#define BLOCK 256

// Per-segment, per-vocab histogram. Zeroed at load; combine_kernel re-zeros
// after consuming -> invariant "all zero on entry" holds every launch/replay.
__device__ int g_counts[MAX_SEGS * VOCAB];

// Recover n0..n3 from (n, ssum=Σt, s0=Σ(t&1), s3=Σ(t==3)) and flush to global.
__device__ __forceinline__ void flush_counts(int seg, int n, int ssum, int s0, int s3) {
    if (n == 0) return;
    int n3 = s3;
    int n1 = s0 - s3;
    int n2 = (ssum - s0 - 2 * s3) >> 1;
    int n0 = n - n1 - n2 - n3;
    int* b = &g_counts[seg * VOCAB];
    if (n0) atomicAdd(b + 0, n0);
    if (n1) atomicAdd(b + 1, n1);
    if (n2) atomicAdd(b + 2, n2);
    if (n3) atomicAdd(b + 3, n3);
}

// dp4a partial sums for 4 packed tokens (one int4 of token words).
__device__ __forceinline__ void dp4_accum(int4 tk, int& ssum, int& s0, int& s3) {
    unsigned a = __byte_perm((unsigned)tk.x, (unsigned)tk.y, 0x0040);
    unsigned b = __byte_perm((unsigned)tk.z, (unsigned)tk.w, 0x0040);
    unsigned p = __byte_perm(a, b, 0x5410);        // low bytes of 4 tokens
    unsigned u  = p >> 1;
    unsigned b0 = p & 0x01010101u;                 // t & 1
    unsigned b3 = p & u & 0x01010101u;             // t == 3
    ssum = __dp4a((int)p,  0x01010101, ssum);
    s0   = __dp4a((int)b0, 0x01010101, s0);
    s3   = __dp4a((int)b3, 0x01010101, s3);
}

// One boundary-path step, pure scalars (no register arrays -> no spills).
#define HIST_STEP(S, TK)                                        \
    do {                                                        \
        if ((S) != cur) {                                       \
            flush_counts(cur, n, ssum, s0, s3);                 \
            n = 0; ssum = 0; s0 = 0; s3 = 0; cur = (S);         \
        }                                                       \
        n++;                                                    \
        ssum += (TK);                                           \
        s0   += (TK) & 1;                                       \
        s3   += ((TK) == 3);                                    \
    } while (0)

__global__ void __launch_bounds__(BLOCK)
hist_kernel(const int* __restrict__ tokens,
            const int* __restrict__ segids,
            int T) {
    // Allow the dependent combine kernel to begin launching/ramping now;
    // it gates on full completion of this grid via cudaGridDependencySynchronize.
    cudaTriggerProgrammaticLaunchCompletion();

    const int chunk_id = blockIdx.x * BLOCK + threadIdx.x;
    const int base = chunk_id * CHUNK;
    if (base >= T) return;

    bool fast = false;
    int seg = 0, ssum = 0, s0 = 0, s3 = 0;

    if (base + CHUNK <= T) {
        // All 4 loads issued before any use: one memory round-trip, MLP=4.
        const int4* t4 = (const int4*)(tokens + base);
        const int4* g4 = (const int4*)(segids + base);
        int4 t0 = __ldg(&t4[0]), t1 = __ldg(&t4[1]);
        int4 g0 = __ldg(&g4[0]), g1 = __ldg(&g4[1]);

        if (g0.x == g1.w) {
            // fast path: whole 8-token chunk in one segment
            dp4_accum(t0, ssum, s0, s3);
            dp4_accum(t1, ssum, s0, s3);
            seg = g0.x;
            fast = true;
        } else {
            // boundary chunk: unrolled over struct fields
            int cur = g0.x;
            int n = 0;
            HIST_STEP(g0.x, t0.x); HIST_STEP(g0.y, t0.y);
            HIST_STEP(g0.z, t0.z); HIST_STEP(g0.w, t0.w);
            HIST_STEP(g1.x, t1.x); HIST_STEP(g1.y, t1.y);
            HIST_STEP(g1.z, t1.z); HIST_STEP(g1.w, t1.w);
            flush_counts(cur, n, ssum, s0, s3);
        }
    } else {
        // tail chunk (scalar, bounds-checked)
        int end = min(T, base + CHUNK);
        int cur = __ldg(&segids[base]);
        int n = 0;
        for (int i = base; i < end; i++) {
            int s = __ldg(&segids[i]);
            int t = __ldg(&tokens[i]);
            HIST_STEP(s, t);
        }
        flush_counts(cur, n, ssum, s0, s3);
    }

    // ---- Warp aggregation: usually all 32 lanes share one segment ----
    unsigned mask = __activemask();           // full warps except grid tail
    int seg0 = __shfl_sync(mask, seg, 0);
    bool uni = __all_sync(mask, fast && (seg == seg0));
    if (uni) {
        int w_ssum = __reduce_add_sync(mask, (unsigned)ssum);
        int w_s0   = __reduce_add_sync(mask, (unsigned)s0);
        int w_s3   = __reduce_add_sync(mask, (unsigned)s3);
        int w_n    = __popc(mask) * CHUNK;
        if ((threadIdx.x & 31) == (unsigned)__ffs(mask) - 1)
            flush_counts(seg0, w_n, w_ssum, w_s0, w_s3);
    } else if (fast) {
        flush_counts(seg, CHUNK, ssum, s0, s3);
    }
}

// ---------------------------------------------------------------------------
// Combine: one warp per segment, one float4 per lane (32 lanes x 4 = 128 dims).
// Launched with PDL: ramps up + loads emb while hist still runs, then gates
// on hist completion before touching g_counts.
// ---------------------------------------------------------------------------
__global__ void __launch_bounds__(BLOCK)
combine_kernel(const float* __restrict__ emb,
               float* __restrict__ out, int R) {
    int tid  = blockIdx.x * BLOCK + threadIdx.x;
    int seg  = tid >> 5;
    int lane = tid & 31;

    // Hist-independent work first: embedding rows into registers.
    const float4* e = (const float4*)emb;
    float4 e0 = __ldg(&e[0 * 32 + lane]);
    float4 e1 = __ldg(&e[1 * 32 + lane]);
    float4 e2 = __ldg(&e[2 * 32 + lane]);
    float4 e3 = __ldg(&e[3 * 32 + lane]);

    // Wait for the full hist grid (all its memory ops visible after this).
    cudaGridDependencySynchronize();

    if (seg >= R) return;

    int4 c = *(const int4*)&g_counts[seg * VOCAB];
    float f0 = (float)c.x, f1 = (float)c.y, f2 = (float)c.z, f3 = (float)c.w;
    float inv = 1.0f / fmaxf(f0 + f1 + f2 + f3, 1.0f);

    float4 r;
    r.x = (f0 * e0.x + f1 * e1.x + f2 * e2.x + f3 * e3.x) * inv;
    r.y = (f0 * e0.y + f1 * e1.y + f2 * e2.y + f3 * e3.y) * inv;
    r.z = (f0 * e0.z + f1 * e1.z + f2 * e2.z + f3 * e3.z) * inv;
    r.w = (f0 * e0.w + f1 * e1.w + f2 * e2.w + f3 * e3.w) * inv;
    ((float4*)out)[seg * 32 + lane] = r;

    __syncwarp();
    if (lane == 0)                            // restore zero invariant
        *(int4*)&g_counts[seg * VOCAB] = make_int4(0, 0, 0, 0);
}

extern "C" void kernel_launch(void* const* d_in, const int* in_sizes, int n_in,
                              void* d_out, int out_size) {
    const int* tokens = (const int*)d_in[0];
    const int* segids = (const int*)d_in[1];
    const float* emb  = (const float*)d_in[2];
    float* out        = (float*)d_out;

    int T = in_sizes[0];
    int R = out_size / DIM;

    int nchunks = (T + CHUNK - 1) / CHUNK;
    int grid = (nchunks + BLOCK - 1) / BLOCK;      // one chunk per thread
    if (grid < 1) grid = 1;
    hist_kernel<<<grid, BLOCK>>>(tokens, segids, T);

    int cthreads = R * 32;
    int cgrid = (cthreads + BLOCK - 1) / BLOCK;

    // PDL launch: combine may start ramping as soon as hist triggers;
    // correctness gated inside by cudaGridDependencySynchronize().
    cudaLaunchConfig_t cfg = {};
    cfg.gridDim  = dim3((unsigned)cgrid, 1, 1);
    cfg.blockDim = dim3(BLOCK, 1, 1);
    cfg.dynamicSmemBytes = 0;
    cudaLaunchAttribute attr[1];
    attr[0].id = cudaLaunchAttributeProgrammaticStreamSerialization;
    attr[0].val.programmaticStreamSerializationAllowed = 1;
    cfg.attrs    = attr;
    cfg.numAttrs = 1;
    cudaLaunchKernelEx(&cfg, combine_kernel, emb, out, R);
}

// round 10
// speedup vs baseline: 1.1696x; 1.1696x over previous
#include <cuda_runtime.h>
#include <cuda_bf16.h>
#include <cstdint>

#define VOCAB 4
#define DIM   128
#define MAX_SEGS 8192
#define CHUNK 16               // tokens per thread; warp covers 512 tokens
#define BLOCK 256

// Per-segment, per-vocab histogram. Zeroed at load; combine_kernel re-zeros
// after consuming -> invariant "all zero on entry" holds every launch/replay.
__device__ int g_counts[MAX_SEGS * VOCAB];

// Recover n0..n3 from (n, ssum=Σt, s0=Σ(t&1), s3=Σ(t==3)) and flush to global.
__device__ __forceinline__ void flush_counts(int seg, int n, int ssum, int s0, int s3) {
    if (n == 0) return;
    int n3 = s3;
    int n1 = s0 - s3;
    int n2 = (ssum - s0 - 2 * s3) >> 1;
    int n0 = n - n1 - n2 - n3;
    int* b = &g_counts[seg * VOCAB];
    if (n0) atomicAdd(b + 0, n0);
    if (n1) atomicAdd(b + 1, n1);
    if (n2) atomicAdd(b + 2, n2);
    if (n3) atomicAdd(b + 3, n3);
}

// dp4a partial sums for 4 packed tokens (one int4 of token words).
__device__ __forceinline__ void dp4_accum(int4 tk, int& ssum, int& s0, int& s3) {
    unsigned a = __byte_perm((unsigned)tk.x, (unsigned)tk.y, 0x0040);
    unsigned b = __byte_perm((unsigned)tk.z, (unsigned)tk.w, 0x0040);
    unsigned p = __byte_perm(a, b, 0x5410);        // low bytes of 4 tokens
    unsigned u  = p >> 1;
    unsigned b0 = p & 0x01010101u;                 // t & 1
    unsigned b3 = p & u & 0x01010101u;             // t == 3
    ssum = __dp4a((int)p,  0x01010101, ssum);
    s0   = __dp4a((int)b0, 0x01010101, s0);
    s3   = __dp4a((int)b3, 0x01010101, s3);
}

// Boundary-path step: flush completed run solo, keep current run in registers.
#define HIST_STEP(S, TK)                                        \
    do {                                                        \
        if ((S) != seg) {                                       \
            flush_counts(seg, n, ssum, s0, s3);                 \
            n = 0; ssum = 0; s0 = 0; s3 = 0; seg = (S);         \
        }                                                       \
        n++;                                                    \
        ssum += (TK);                                           \
        s0   += (TK) & 1;                                       \
        s3   += ((TK) == 3);                                    \
    } while (0)

__global__ void __launch_bounds__(BLOCK)
hist_kernel(const int* __restrict__ tokens,
            const int* __restrict__ segids,
            int T) {
    const int chunk_id = blockIdx.x * BLOCK + threadIdx.x;
    const int base = chunk_id * CHUNK;
    if (base >= T) return;

    // Thread's final run accumulator (joins the group-aggregated flush below).
    int seg = 0, n = 0, ssum = 0, s0 = 0, s3 = 0;

    if (base + CHUNK <= T) {
        const int4* t4 = (const int4*)(tokens + base);
        const int4* g4 = (const int4*)(segids + base);
        // Sampled segids: only first + last vector needed on the fast path.
        int4 t0 = __ldg(&t4[0]), t1 = __ldg(&t4[1]),
             t2 = __ldg(&t4[2]), t3 = __ldg(&t4[3]);
        int4 ga = __ldg(&g4[0]), gb = __ldg(&g4[3]);

        if (ga.x == gb.w) {
            // fast path: whole 16-token chunk in one segment
            dp4_accum(t0, ssum, s0, s3);
            dp4_accum(t1, ssum, s0, s3);
            dp4_accum(t2, ssum, s0, s3);
            dp4_accum(t3, ssum, s0, s3);
            seg = ga.x;
            n = CHUNK;
        } else {
            // boundary chunk (~1.6%): fetch the middle segid vectors now
            int4 g1 = __ldg(&g4[1]), g2 = __ldg(&g4[2]);
            seg = ga.x;
            HIST_STEP(ga.x, t0.x); HIST_STEP(ga.y, t0.y);
            HIST_STEP(ga.z, t0.z); HIST_STEP(ga.w, t0.w);
            HIST_STEP(g1.x, t1.x); HIST_STEP(g1.y, t1.y);
            HIST_STEP(g1.z, t1.z); HIST_STEP(g1.w, t1.w);
            HIST_STEP(g2.x, t2.x); HIST_STEP(g2.y, t2.y);
            HIST_STEP(g2.z, t2.z); HIST_STEP(g2.w, t2.w);
            HIST_STEP(gb.x, t3.x); HIST_STEP(gb.y, t3.y);
            HIST_STEP(gb.z, t3.z); HIST_STEP(gb.w, t3.w);
            // last run stays in (seg, n, ssum, s0, s3)
        }
    } else {
        // tail chunk (scalar, bounds-checked)
        int end = min(T, base + CHUNK);
        seg = __ldg(&segids[base]);
        for (int i = base; i < end; i++) {
            int s = __ldg(&segids[i]);
            int t = __ldg(&tokens[i]);
            HIST_STEP(s, t);
        }
    }

    // ---- Group-aggregated flush: lanes sharing a segment reduce together ----
    unsigned act = __activemask();
    unsigned grp = __match_any_sync(act, seg);
    int gn    = (int)__reduce_add_sync(grp, (unsigned)n);
    int gssum = (int)__reduce_add_sync(grp, (unsigned)ssum);
    int gs0   = (int)__reduce_add_sync(grp, (unsigned)s0);
    int gs3   = (int)__reduce_add_sync(grp, (unsigned)s3);
    if ((threadIdx.x & 31) == (unsigned)__ffs(grp) - 1)
        flush_counts(seg, gn, gssum, gs0, gs3);
}

// ---------------------------------------------------------------------------
// Combine: one warp per segment, one float4 per lane (32 lanes x 4 = 128 dims).
// ---------------------------------------------------------------------------
__global__ void __launch_bounds__(BLOCK)
combine_kernel(const float* __restrict__ emb,
               float* __restrict__ out, int R) {
    int tid  = blockIdx.x * BLOCK + threadIdx.x;
    int seg  = tid >> 5;
    int lane = tid & 31;
    if (seg >= R) return;

    int4 c = *(const int4*)&g_counts[seg * VOCAB];
    float f0 = (float)c.x, f1 = (float)c.y, f2 = (float)c.z, f3 = (float)c.w;
    float inv = 1.0f / fmaxf(f0 + f1 + f2 + f3, 1.0f);

    const float4* e = (const float4*)emb;
    float4 e0 = __ldg(&e[0 * 32 + lane]);
    float4 e1 = __ldg(&e[1 * 32 + lane]);
    float4 e2 = __ldg(&e[2 * 32 + lane]);
    float4 e3 = __ldg(&e[3 * 32 + lane]);

    float4 r;
    r.x = (f0 * e0.x + f1 * e1.x + f2 * e2.x + f3 * e3.x) * inv;
    r.y = (f0 * e0.y + f1 * e1.y + f2 * e2.y + f3 * e3.y) * inv;
    r.z = (f0 * e0.z + f1 * e1.z + f2 * e2.z + f3 * e3.z) * inv;
    r.w = (f0 * e0.w + f1 * e1.w + f2 * e2.w + f3 * e3.w) * inv;
    ((float4*)out)[seg * 32 + lane] = r;

    __syncwarp();
    if (lane == 0)                            // restore zero invariant
        *(int4*)&g_counts[seg * VOCAB] = make_int4(0, 0, 0, 0);
}

extern "C" void kernel_launch(void* const* d_in, const int* in_sizes, int n_in,
                              void* d_out, int out_size) {
    const int* tokens = (const int*)d_in[0];
    const int* segids = (const int*)d_in[1];
    const float* emb  = (const float*)d_in[2];
    float* out        = (float*)d_out;

    int T = in_sizes[0];
    int R = out_size / DIM;

    int nchunks = (T + CHUNK - 1) / CHUNK;
    int grid = (nchunks + BLOCK - 1) / BLOCK;      // one chunk per thread
    if (grid < 1) grid = 1;
    hist_kernel<<<grid, BLOCK>>>(tokens, segids, T);

    int cthreads = R * 32;
    int cgrid = (cthreads + BLOCK - 1) / BLOCK;
    combine_kernel<<<cgrid, BLOCK>>>(emb, out, R);
}